// round 14
// baseline (speedup 1.0000x reference)
#include <cuda_runtime.h>
#include <cstdint>
#include <math.h>

// Problem constants
#define TPRIME 510
#define BATCH  32
#define CIN    128
#define TLEN   1024
#define FDIM   256
#define KCONV  640            // CIN * KW
#define HDIM   512
#define GDIM   2048           // 4*H
#define M_ROWS (TPRIME*BATCH) // 16320
#define NCTA_R 128            // persistent CTAs for recurrence

// recurrence smem layout
// h slab per staging warp: 32 b rows x 64 k; row = 4 chunks of 16 floats at
// 20-float stride (chunk shim) -> warp's 4 ks-groups hit disjoint banks
#define HCH    20             // chunk stride (floats)
#define HBROW  80             // h row stride (floats) = 4*HCH
#define HSWARP (32*HBROW)     // 2560 floats per warp slab
#define PSTR   20             // part: b stride
#define SKS    648            // part: ks stride (32*20 + 8)

// ---------------- packed f32x2 helpers (Blackwell FFMA2 path) ----------------
__device__ __forceinline__ void ffma2(unsigned long long &d,
                                      unsigned long long a,
                                      unsigned long long b) {
    asm("fma.rn.f32x2 %0, %1, %2, %0;" : "+l"(d) : "l"(a), "l"(b));
}
__device__ __forceinline__ unsigned long long pk2(float x) {
    unsigned long long r;
    asm("mov.b64 %0, {%1, %1};" : "=l"(r) : "f"(x));
    return r;
}
__device__ __forceinline__ float2 upk(unsigned long long v) {
    float2 r;
    asm("mov.b64 {%0, %1}, %2;" : "=f"(r.x), "=f"(r.y) : "l"(v));
    return r;
}

// ---------------- scratch -----------------------------------------------------
__device__ float g_Wr[FDIM*KCONV];                    // conv_w transposed [f][k][c]
__device__ float g_feats[(size_t)M_ROWS*FDIM];        // conv output [m][F]
__device__ float g_h[2][BATCH*HDIM];                  // double-buffered hidden state
__device__ float g_pu[2][BATCH*NCTA_R];               // partial u-dot [b][cta]
__device__ unsigned g_flags[NCTA_R*32];               // per-CTA step flags, 128B apart

// ---------------- prep --------------------------------------------------------
__global__ void prep_kernel(const float* __restrict__ conv_w)
{
    int stride = gridDim.x * blockDim.x;
    int i0 = blockIdx.x * blockDim.x + threadIdx.x;
    for (int i = i0; i < FDIM*KCONV; i += stride) {
        int f = i / KCONV;
        int rem = i - f*KCONV;
        int k = rem >> 7;
        int c = rem & 127;
        g_Wr[i] = conv_w[f*KCONV + c*5 + k];
    }
    for (int i = i0; i < BATCH*HDIM; i += stride) g_h[0][i] = 0.f;
    for (int i = i0; i < NCTA_R*32; i += stride) g_flags[i] = 0u;
}

// ---------------- conv as GEMM: [16320 x 640] * [640 x 256]^T -----------------
__global__ __launch_bounds__(256)
void conv_gemm(const float* __restrict__ x,
               const float* __restrict__ cb,
               const float* __restrict__ gam,
               const float* __restrict__ bet,
               const float* __restrict__ mu,
               const float* __restrict__ var)
{
    __shared__ float As[16][132];
    __shared__ float Bs[16][132];
    const int tid  = threadIdx.x;
    const int mblk = blockIdx.y * 128;
    const int nblk = blockIdx.x * 128;
    const int lrow = tid >> 1;
    const int lk   = (tid & 1) * 8;

    const int m = mblk + lrow;
    const bool mvalid = (m < M_ROWS);
    const float* arow = x;
    if (mvalid) {
        int t = m >> 5, b = m & 31;
        arow = x + (size_t)b * (TLEN*CIN) + (size_t)t * (2*CIN);
    }
    const float* brow = g_Wr + (size_t)(nblk + lrow) * KCONV;

    unsigned long long acc2[8][4];
#pragma unroll
    for (int i = 0; i < 8; i++)
#pragma unroll
        for (int j = 0; j < 4; j++) acc2[i][j] = 0ull;

    const int ty = tid >> 4, tx = tid & 15;

    for (int k0 = 0; k0 < KCONV; k0 += 16) {
        float4 a0 = make_float4(0.f,0.f,0.f,0.f), a1 = a0;
        if (mvalid) {
            a0 = *(const float4*)(arow + k0 + lk);
            a1 = *(const float4*)(arow + k0 + lk + 4);
        }
        float4 b0 = *(const float4*)(brow + k0 + lk);
        float4 b1 = *(const float4*)(brow + k0 + lk + 4);
        __syncthreads();
        As[lk+0][lrow]=a0.x; As[lk+1][lrow]=a0.y; As[lk+2][lrow]=a0.z; As[lk+3][lrow]=a0.w;
        As[lk+4][lrow]=a1.x; As[lk+5][lrow]=a1.y; As[lk+6][lrow]=a1.z; As[lk+7][lrow]=a1.w;
        Bs[lk+0][lrow]=b0.x; Bs[lk+1][lrow]=b0.y; Bs[lk+2][lrow]=b0.z; Bs[lk+3][lrow]=b0.w;
        Bs[lk+4][lrow]=b1.x; Bs[lk+5][lrow]=b1.y; Bs[lk+6][lrow]=b1.z; Bs[lk+7][lrow]=b1.w;
        __syncthreads();
#pragma unroll
        for (int k = 0; k < 16; k++) {
            float a[8];
            *(float4*)&a[0] = *(const float4*)&As[k][ty*4];
            *(float4*)&a[4] = *(const float4*)&As[k][ty*4+64];
            ulonglong2 bq0 = *(const ulonglong2*)&Bs[k][tx*4];
            ulonglong2 bq1 = *(const ulonglong2*)&Bs[k][tx*4+64];
#pragma unroll
            for (int i = 0; i < 8; i++) {
                unsigned long long aa = pk2(a[i]);
                ffma2(acc2[i][0], aa, bq0.x);
                ffma2(acc2[i][1], aa, bq0.y);
                ffma2(acc2[i][2], aa, bq1.x);
                ffma2(acc2[i][3], aa, bq1.y);
            }
        }
    }
#pragma unroll
    for (int j2 = 0; j2 < 4; j2++) {
        int nrel = (j2 < 2) ? (tx*4 + j2*2) : (64 + tx*4 + (j2-2)*2);
#pragma unroll
        for (int h = 0; h < 2; h++) {
            int n = nblk + nrel + h;
            float invv = gam[n] * rsqrtf(var[n] + 1e-5f);
            float addv = bet[n] - mu[n]*invv;
            float cbv  = cb[n];
#pragma unroll
            for (int i = 0; i < 8; i++) {
                int mm = mblk + ((i < 4) ? (ty*4 + i) : (64 + ty*4 + i - 4));
                if (mm < M_ROWS) {
                    float2 p = upk(acc2[i][j2]);
                    float v = ((h == 0) ? p.x : p.y) + cbv;
                    v = fmaxf(v, 0.f);
                    g_feats[(size_t)mm*FDIM + n] = v*invv + addv;
                }
            }
        }
    }
}

// ---------------- persistent skip-LSTM recurrence (xproj fused in) ------------
__device__ __forceinline__ float sigf(float v) {
    return __fdividef(1.f, 1.f + __expf(-v));
}
__device__ __forceinline__ float tanh_fast(float v) {
    float x = fminf(fmaxf(v, -15.f), 15.f);
    float e = __expf(2.f * x);
    return __fdividef(e - 1.f, e + 1.f);
}

// xp stage: feats[tt] -> fts (16 slices x [b][PSTR] with float4 shim layout)
__device__ __forceinline__ void xp_stage(float* fts, int tt, int tid)
{
    const float4* fsrc = reinterpret_cast<const float4*>(g_feats) + (size_t)tt * 2048;
#pragma unroll
    for (int i = 0; i < 8; i++) {
        int f = i*256 + tid;                 // float4 index: b = f>>6, k4 = f&63
        float4 v = __ldcg(fsrc + f);
        int b = f >> 6, k4 = f & 63;
        fts[(size_t)(k4 >> 2)*SKS + b*PSTR + (k4 & 3)*4 + 0] = v.x;
        *(float4*)&fts[(k4 >> 2)*SKS + b*PSTR + (k4 & 3)*4] = v;
    }
}

// xp dot: 1 row (r16), k-slice 16 (ks16), writes part slices 0..15
__device__ __forceinline__ void xp_dot(const float* fts, float* part,
                                       const unsigned long long* wihreg,
                                       int r, int ks)
{
    const float* fb = fts + ks*SKS;
#pragma unroll 4
    for (int b = 0; b < 32; b++) {
        const float* fp = fb + b*PSTR;
        ulonglong2 f0 = *(const ulonglong2*)(fp);
        ulonglong2 f1 = *(const ulonglong2*)(fp + 4);
        ulonglong2 f2 = *(const ulonglong2*)(fp + 8);
        ulonglong2 f3 = *(const ulonglong2*)(fp + 12);
        unsigned long long a = 0ull;
        ffma2(a, wihreg[0], f0.x); ffma2(a, wihreg[1], f0.y);
        ffma2(a, wihreg[2], f1.x); ffma2(a, wihreg[3], f1.y);
        ffma2(a, wihreg[4], f2.x); ffma2(a, wihreg[5], f2.y);
        ffma2(a, wihreg[6], f3.x); ffma2(a, wihreg[7], f3.y);
        float2 p = upk(a);
        part[ks*SKS + b*PSTR + r] = p.x + p.y;
    }
}

__global__ __launch_bounds__(256)
void recur_kernel(const float* __restrict__ w_hh,
                  const float* __restrict__ w_ih,
                  const float* __restrict__ b_ih,
                  const float* __restrict__ b_hh,
                  const float* __restrict__ w_uh,
                  const float* __restrict__ b_uh,
                  float* __restrict__ out)
{
    extern __shared__ float sm[];
    float* hs   = sm;                    // [8 warps][32 b][HBROW] h slabs (chunked)
    float* part = hs + 8*HSWARP;         // [32 ks][32 b][PSTR]
    float* fts  = part + 16*SKS;         // overlay on part slices 16..31
    float* us   = part + 32*SKS;         // [32] u state

    const int tid  = threadIdx.x;
    const int warp = tid >> 5;
    const int lane = tid & 31;
    const int cta  = blockIdx.x;
    const int j0   = cta * 4;

    // h-GEMM mapping: 2 rows per thread
    const int r   = tid & 7;             // rows r and r+8
    const int ksg = tid >> 3;            // k-chunk 0..31 (16 k each)
    // xp mapping: 1 row per thread
    const int rx  = tid & 15;
    const int ksx = tid >> 4;            // 0..15 (16 k each of FDIM=256)

    // ---- w_hh slices into registers: rows r (q=r>>2) and r+8 (q+2), k [ksg*16,+16)
    ulonglong2 wa[4], wb[4];
    unsigned long long wihreg[8];
    {
        int q0 = r >> 2, jl0 = r & 3;
        const float* w0 = w_hh + (size_t)(q0*HDIM + j0 + jl0) * HDIM + ksg*16;
        const float* w1 = w_hh + (size_t)((q0+2)*HDIM + j0 + jl0) * HDIM + ksg*16;
#pragma unroll
        for (int i = 0; i < 4; i++) {
            wa[i] = *(const ulonglong2*)(w0 + i*4);
            wb[i] = *(const ulonglong2*)(w1 + i*4);
        }
        int qx = rx >> 2, jlx = rx & 3;
        const float* w2 = w_ih + (size_t)(qx*HDIM + j0 + jlx) * FDIM + ksx*16;
#pragma unroll
        for (int i = 0; i < 4; i++) {
            ulonglong2 v = *(const ulonglong2*)(w2 + i*4);
            wihreg[2*i]   = v.x;
            wihreg[2*i+1] = v.y;
        }
    }
    if (tid < 32) us[tid] = 1.f;

    const float wuh_l = (tid < 128) ? w_uh[j0 + (tid & 3)] : 0.f;
    const float buh   = b_uh[0];

    float biasr[4];
    if (tid < 128) {
        int jl = tid & 3;
#pragma unroll
        for (int q = 0; q < 4; q++)
            biasr[q] = b_ih[q*HDIM + j0 + jl] + b_hh[q*HDIM + j0 + jl];
    }
    __syncthreads();

    // ---- prologue: xg for t=0 --------------------------------------------
    float xg[4] = {0.f, 0.f, 0.f, 0.f};
    {
        xp_stage(fts, 0, tid);
        __syncthreads();
        xp_dot(fts, part, wihreg, rx, ksx);
        __syncthreads();
        if (tid < 128) {
            int b = tid >> 2, jl = tid & 3;
#pragma unroll
            for (int q = 0; q < 4; q++) {
                float s = biasr[q];
                const float* pp = part + b*PSTR + q*4 + jl;
#pragma unroll
                for (int k2 = 0; k2 < 16; k2++) s += pp[k2*SKS];
                xg[q] = s;
            }
        }
        __syncthreads();
    }

    float c_reg = 0.f;                   // cell state for (b = tid>>2, jl = tid&3)
    float* hswp = hs + warp*HSWARP;

    for (int t = 0; t < TPRIME; t++) {
        const int ph = t & 1;

        // ---- load this warp's h slice: h[b][64*warp .. +64], 16 float4/lane --
        const float4* hsrc = reinterpret_cast<const float4*>(g_h[ph]);
        float4 hv[16];
#pragma unroll
        for (int i = 0; i < 16; i++) {
            int f = i*32 + lane;
            int b = f >> 4, k4 = f & 15;
            hv[i] = __ldcg(hsrc + b*128 + warp*16 + k4);
        }

        // ---- u update from previous step's partials (tid<128) ----------------
        if (t > 0 && tid < 128) {
            const float4* pp = (const float4*)&g_pu[(t-1)&1][(tid>>2)*NCTA_R + (tid&3)*32];
            float s = 0.f;
#pragma unroll
            for (int i = 0; i < 8; i++) {
                float4 v = __ldcg(pp + i);
                s += v.x + v.y + v.z + v.w;
            }
            s += __shfl_down_sync(0xffffffffu, s, 1);
            s += __shfl_down_sync(0xffffffffu, s, 2);
            if ((tid & 3) == 0) {
                int b = tid >> 2;
                float du = sigf(s + buh);
                float u  = us[b];
                float ub = rintf(u);
                us[b] = ub*du + (1.f-ub)*(u + fminf(du, 1.f-u));
            }
        }

        // ---- stage slice into smem (chunked rows) ----------------------------
#pragma unroll
        for (int i = 0; i < 16; i++) {
            int f = i*32 + lane;
            int b = f >> 4, k4 = f & 15;
            int off = (k4 >> 2)*HCH + (k4 & 3)*4;
            *(float4*)&hswp[b*HBROW + off] = hv[i];
        }
        __syncwarp();

        // ---- GEMM: rows {r, r+8} x h[b][ksg*16 .. +16] -----------------------
        {
            const float* slab = hs + (ksg >> 2)*HSWARP + (ksg & 3)*HCH;
#pragma unroll 4
            for (int b = 0; b < 32; b++) {
                const float* hp = slab + b*HBROW;
                ulonglong2 h0 = *(const ulonglong2*)(hp);
                ulonglong2 h1 = *(const ulonglong2*)(hp + 4);
                ulonglong2 h2 = *(const ulonglong2*)(hp + 8);
                ulonglong2 h3 = *(const ulonglong2*)(hp + 12);
                unsigned long long aA = 0ull, aB = 0ull;
                ffma2(aA, wa[0].x, h0.x); ffma2(aA, wa[0].y, h0.y);
                ffma2(aA, wa[1].x, h1.x); ffma2(aA, wa[1].y, h1.y);
                ffma2(aA, wa[2].x, h2.x); ffma2(aA, wa[2].y, h2.y);
                ffma2(aA, wa[3].x, h3.x); ffma2(aA, wa[3].y, h3.y);
                ffma2(aB, wb[0].x, h0.x); ffma2(aB, wb[0].y, h0.y);
                ffma2(aB, wb[1].x, h1.x); ffma2(aB, wb[1].y, h1.y);
                ffma2(aB, wb[2].x, h2.x); ffma2(aB, wb[2].y, h2.y);
                ffma2(aB, wb[3].x, h3.x); ffma2(aB, wb[3].y, h3.y);
                float2 pA = upk(aA), pB = upk(aB);
                *(float2*)&part[(size_t)ksg*SKS + b*PSTR + r*2] =
                    make_float2(pA.x + pA.y, pB.x + pB.y);
            }
        }
        __syncthreads();

        // ---- fused k-reduce + cell update (tid<128: b=tid>>2, jl=tid&3) ------
        if (tid < 128) {
            int b  = tid >> 2;
            int jl = tid & 3;
            float g4[4];
#pragma unroll
            for (int q = 0; q < 4; q++) {
                int r0 = q*4 + jl;
                int po = (r0 & 7)*2 + (r0 >> 3);
                float s = xg[q];
                const float* pp = part + b*PSTR + po;
#pragma unroll
                for (int k2 = 0; k2 < 32; k2++) s += pp[(size_t)k2*SKS];
                g4[q] = s;
            }
            float u  = us[b];
            float ub = rintf(u);
            float ct = sigf(g4[1])*c_reg + sigf(g4[0])*tanh_fast(g4[2]);
            float ht = sigf(g4[3])*tanh_fast(ct);
            int hidx = j0 + jl;
            int hw = hidx >> 6;
            int ho = hidx & 63;
            int hoff = (ho >> 4)*HCH + (ho & 15);
            float hprev = hs[hw*HSWARP + b*HBROW + hoff];
            float cn = ub*ct + (1.f-ub)*c_reg;
            float hn = ub*ht + (1.f-ub)*hprev;
            c_reg = cn;

            __stcg(&g_h[ph^1][b*HDIM + j0 + jl], hn);
            if (t == TPRIME-1) out[b*HDIM + j0 + jl] = hn;

            float pv = cn * wuh_l;
            pv += __shfl_down_sync(0xffffffffu, pv, 1);
            pv += __shfl_down_sync(0xffffffffu, pv, 2);
            if (jl == 0) __stcg(&g_pu[ph][b*NCTA_R + cta], pv);
        }
        __syncthreads();

        if (t < TPRIME-1) {
            // ---- release flag FIRST ------------------------------------------
            if (tid == 0) {
                asm volatile("st.release.gpu.global.u32 [%0], %1;"
                             :: "l"(&g_flags[cta*32]), "r"((unsigned)(t+1)) : "memory");
            }

            // ---- xp for step t+1 in the barrier's shadow ---------------------
            xp_stage(fts, t+1, tid);
            __syncthreads();
            xp_dot(fts, part, wihreg, rx, ksx);
            __syncthreads();
            if (tid < 128) {
                int b = tid >> 2, jl = tid & 3;
#pragma unroll
                for (int q = 0; q < 4; q++) {
                    float s = biasr[q];
                    const float* pp = part + b*PSTR + q*4 + jl;
#pragma unroll
                    for (int k2 = 0; k2 < 16; k2++) s += pp[k2*SKS];
                    xg[q] = s;
                }
            }

            // ---- paced poll --------------------------------------------------
            if (tid < NCTA_R) {
                const unsigned tgt = (unsigned)(t+1);
                unsigned v;
                asm volatile("ld.acquire.gpu.global.u32 %0, [%1];"
                             : "=r"(v) : "l"(&g_flags[tid*32]) : "memory");
                while (v < tgt) {
                    __nanosleep(40);
                    asm volatile("ld.acquire.gpu.global.u32 %0, [%1];"
                                 : "=r"(v) : "l"(&g_flags[tid*32]) : "memory");
                }
            }
            __syncthreads();
        }
    }
}

// ---------------- launch -----------------------------------------------------
extern "C" void kernel_launch(void* const* d_in, const int* in_sizes, int n_in,
                              void* d_out, int out_size)
{
    const float* x      = (const float*)d_in[0];
    const float* conv_w = (const float*)d_in[1];
    const float* conv_b = (const float*)d_in[2];
    const float* gam    = (const float*)d_in[3];
    const float* bet    = (const float*)d_in[4];
    const float* mu     = (const float*)d_in[5];
    const float* var    = (const float*)d_in[6];
    const float* w_ih   = (const float*)d_in[7];
    const float* w_hh   = (const float*)d_in[8];
    const float* b_ih   = (const float*)d_in[9];
    const float* b_hh   = (const float*)d_in[10];
    const float* w_uh   = (const float*)d_in[11];
    const float* b_uh   = (const float*)d_in[12];

    const int smem_recur = (8*HSWARP + 32*SKS + 64) * (int)sizeof(float);
    cudaFuncSetAttribute(recur_kernel, cudaFuncAttributeMaxDynamicSharedMemorySize, smem_recur);

    prep_kernel<<<64, 256>>>(conv_w);
    conv_gemm<<<dim3(2, 128), 256>>>(x, conv_b, gam, bet, mu, var);
    recur_kernel<<<NCTA_R, 256, smem_recur>>>(w_hh, w_ih, b_ih, b_hh, w_uh, b_uh,
                                              (float*)d_out);
}

// round 15
// speedup vs baseline: 1.0036x; 1.0036x over previous
#include <cuda_runtime.h>
#include <cstdint>
#include <math.h>

// Problem constants
#define TPRIME 510
#define BATCH  32
#define CIN    128
#define TLEN   1024
#define FDIM   256
#define KCONV  640            // CIN * KW
#define HDIM   512
#define GDIM   2048           // 4*H
#define M_ROWS (TPRIME*BATCH) // 16320
#define NCTA_R 128            // persistent CTAs for recurrence
#define NTH_R  512            // 16 warps

// recurrence smem layout: 16 slabs (one per ks slice of 32 k), each 32 b rows
// of 36-float stride (32 k + 4 pad); slab stride 1156 = 32*36+4 (== 4 mod 32
// so adjacent-slab broadcast reads hit disjoint bank quads)
#define HROWS  36
#define SLAB   1156
#define PSTR   20             // part: b stride
#define SKS    648            // part: ks stride (32*20 + 8)

// ---------------- packed f32x2 helpers (Blackwell FFMA2 path) ----------------
__device__ __forceinline__ void ffma2(unsigned long long &d,
                                      unsigned long long a,
                                      unsigned long long b) {
    asm("fma.rn.f32x2 %0, %1, %2, %0;" : "+l"(d) : "l"(a), "l"(b));
}
__device__ __forceinline__ unsigned long long pk2(float x) {
    unsigned long long r;
    asm("mov.b64 %0, {%1, %1};" : "=l"(r) : "f"(x));
    return r;
}
__device__ __forceinline__ float2 upk(unsigned long long v) {
    float2 r;
    asm("mov.b64 {%0, %1}, %2;" : "=f"(r.x), "=f"(r.y) : "l"(v));
    return r;
}

// ---------------- scratch -----------------------------------------------------
__device__ float g_Wr[FDIM*KCONV];                    // conv_w transposed [f][k][c]
__device__ float g_feats[(size_t)M_ROWS*FDIM];        // conv output [m][F]
__device__ float g_h[2][BATCH*HDIM];                  // double-buffered hidden state
__device__ float g_pu[2][BATCH*NCTA_R];               // partial u-dot [b][cta]
__device__ unsigned g_flags[NCTA_R*32];               // per-CTA step flags, 128B apart

// ---------------- prep --------------------------------------------------------
__global__ void prep_kernel(const float* __restrict__ conv_w)
{
    int stride = gridDim.x * blockDim.x;
    int i0 = blockIdx.x * blockDim.x + threadIdx.x;
    for (int i = i0; i < FDIM*KCONV; i += stride) {
        int f = i / KCONV;
        int rem = i - f*KCONV;
        int k = rem >> 7;
        int c = rem & 127;
        g_Wr[i] = conv_w[f*KCONV + c*5 + k];
    }
    for (int i = i0; i < BATCH*HDIM; i += stride) g_h[0][i] = 0.f;
    for (int i = i0; i < NCTA_R*32; i += stride) g_flags[i] = 0u;
}

// ---------------- conv as GEMM: [16320 x 640] * [640 x 256]^T -----------------
__global__ __launch_bounds__(256)
void conv_gemm(const float* __restrict__ x,
               const float* __restrict__ cb,
               const float* __restrict__ gam,
               const float* __restrict__ bet,
               const float* __restrict__ mu,
               const float* __restrict__ var)
{
    __shared__ float As[16][132];
    __shared__ float Bs[16][132];
    const int tid  = threadIdx.x;
    const int mblk = blockIdx.y * 128;
    const int nblk = blockIdx.x * 128;
    const int lrow = tid >> 1;
    const int lk   = (tid & 1) * 8;

    const int m = mblk + lrow;
    const bool mvalid = (m < M_ROWS);
    const float* arow = x;
    if (mvalid) {
        int t = m >> 5, b = m & 31;
        arow = x + (size_t)b * (TLEN*CIN) + (size_t)t * (2*CIN);
    }
    const float* brow = g_Wr + (size_t)(nblk + lrow) * KCONV;

    unsigned long long acc2[8][4];
#pragma unroll
    for (int i = 0; i < 8; i++)
#pragma unroll
        for (int j = 0; j < 4; j++) acc2[i][j] = 0ull;

    const int ty = tid >> 4, tx = tid & 15;

    for (int k0 = 0; k0 < KCONV; k0 += 16) {
        float4 a0 = make_float4(0.f,0.f,0.f,0.f), a1 = a0;
        if (mvalid) {
            a0 = *(const float4*)(arow + k0 + lk);
            a1 = *(const float4*)(arow + k0 + lk + 4);
        }
        float4 b0 = *(const float4*)(brow + k0 + lk);
        float4 b1 = *(const float4*)(brow + k0 + lk + 4);
        __syncthreads();
        As[lk+0][lrow]=a0.x; As[lk+1][lrow]=a0.y; As[lk+2][lrow]=a0.z; As[lk+3][lrow]=a0.w;
        As[lk+4][lrow]=a1.x; As[lk+5][lrow]=a1.y; As[lk+6][lrow]=a1.z; As[lk+7][lrow]=a1.w;
        Bs[lk+0][lrow]=b0.x; Bs[lk+1][lrow]=b0.y; Bs[lk+2][lrow]=b0.z; Bs[lk+3][lrow]=b0.w;
        Bs[lk+4][lrow]=b1.x; Bs[lk+5][lrow]=b1.y; Bs[lk+6][lrow]=b1.z; Bs[lk+7][lrow]=b1.w;
        __syncthreads();
#pragma unroll
        for (int k = 0; k < 16; k++) {
            float a[8];
            *(float4*)&a[0] = *(const float4*)&As[k][ty*4];
            *(float4*)&a[4] = *(const float4*)&As[k][ty*4+64];
            ulonglong2 bq0 = *(const ulonglong2*)&Bs[k][tx*4];
            ulonglong2 bq1 = *(const ulonglong2*)&Bs[k][tx*4+64];
#pragma unroll
            for (int i = 0; i < 8; i++) {
                unsigned long long aa = pk2(a[i]);
                ffma2(acc2[i][0], aa, bq0.x);
                ffma2(acc2[i][1], aa, bq0.y);
                ffma2(acc2[i][2], aa, bq1.x);
                ffma2(acc2[i][3], aa, bq1.y);
            }
        }
    }
#pragma unroll
    for (int j2 = 0; j2 < 4; j2++) {
        int nrel = (j2 < 2) ? (tx*4 + j2*2) : (64 + tx*4 + (j2-2)*2);
#pragma unroll
        for (int h = 0; h < 2; h++) {
            int n = nblk + nrel + h;
            float invv = gam[n] * rsqrtf(var[n] + 1e-5f);
            float addv = bet[n] - mu[n]*invv;
            float cbv  = cb[n];
#pragma unroll
            for (int i = 0; i < 8; i++) {
                int mm = mblk + ((i < 4) ? (ty*4 + i) : (64 + ty*4 + i - 4));
                if (mm < M_ROWS) {
                    float2 p = upk(acc2[i][j2]);
                    float v = ((h == 0) ? p.x : p.y) + cbv;
                    v = fmaxf(v, 0.f);
                    g_feats[(size_t)mm*FDIM + n] = v*invv + addv;
                }
            }
        }
    }
}

// ---------------- persistent skip-LSTM recurrence (xproj fused in) ------------
__device__ __forceinline__ float sigf(float v) {
    return __fdividef(1.f, 1.f + __expf(-v));
}
__device__ __forceinline__ float tanh_fast(float v) {
    float x = fminf(fmaxf(v, -15.f), 15.f);
    float e = __expf(2.f * x);
    return __fdividef(e - 1.f, e + 1.f);
}

// xp stage: feats[tt] -> fts (16 slices x [b][PSTR]), 512 threads
__device__ __forceinline__ void xp_stage(float* fts, int tt, int tid)
{
    const float4* fsrc = reinterpret_cast<const float4*>(g_feats) + (size_t)tt * 2048;
#pragma unroll
    for (int i = 0; i < 4; i++) {
        int f = i*512 + tid;                 // float4 index: b = f>>6, k4 = f&63
        float4 v = __ldcg(fsrc + f);
        int b = f >> 6, k4 = f & 63;
        *(float4*)&fts[(size_t)(k4 >> 2)*SKS + b*PSTR + (k4 & 3)*4] = v;
    }
}

// xp dot: row r, k-slice ks (16 k), b range [b0, b0+16)
__device__ __forceinline__ void xp_dot(const float* fts, float* part,
                                       const unsigned long long* wihreg,
                                       int r, int ks, int b0)
{
    const float* fb = fts + ks*SKS;
#pragma unroll 4
    for (int bi = 0; bi < 16; bi++) {
        int b = b0 + bi;
        const float* fp = fb + b*PSTR;
        ulonglong2 f0 = *(const ulonglong2*)(fp);
        ulonglong2 f1 = *(const ulonglong2*)(fp + 4);
        ulonglong2 f2 = *(const ulonglong2*)(fp + 8);
        ulonglong2 f3 = *(const ulonglong2*)(fp + 12);
        unsigned long long a = 0ull;
        ffma2(a, wihreg[0], f0.x); ffma2(a, wihreg[1], f0.y);
        ffma2(a, wihreg[2], f1.x); ffma2(a, wihreg[3], f1.y);
        ffma2(a, wihreg[4], f2.x); ffma2(a, wihreg[5], f2.y);
        ffma2(a, wihreg[6], f3.x); ffma2(a, wihreg[7], f3.y);
        float2 p = upk(a);
        part[ks*SKS + b*PSTR + r] = p.x + p.y;
    }
}

__global__ __launch_bounds__(NTH_R)
void recur_kernel(const float* __restrict__ w_hh,
                  const float* __restrict__ w_ih,
                  const float* __restrict__ b_ih,
                  const float* __restrict__ b_hh,
                  const float* __restrict__ w_uh,
                  const float* __restrict__ b_uh,
                  float* __restrict__ out)
{
    extern __shared__ float sm[];
    float* hs   = sm;                    // [16 slabs][32 b][HROWS] (+pad)
    float* part = hs + 16*SLAB;          // [16 ks][32 b][PSTR]
    float* fts  = part + 16*SKS;         // [16 ks][32 b][PSTR]
    float* us   = fts + 16*SKS;          // [32] u state

    const int tid  = threadIdx.x;
    const int warp = tid >> 5;
    const int lane = tid & 31;
    const int cta  = blockIdx.x;
    const int j0   = cta * 4;

    const int r  = tid & 15;             // row 0..15 (q = r>>2, jl = r&3)
    const int ks = (tid >> 4) & 15;      // k-slice 0..15 (32 k each for h, 16 for xp)
    const int b0 = (tid >> 8) * 16;      // b half: 0 or 16

    // ---- w_hh slice: row (q*512 + j0 + jl), k in [ks*32, +32) -> 8 ull2
    ulonglong2 wreg[8];
    unsigned long long wihreg[8];        // w_ih row r, k in [ks*16, +16)
    {
        int q = r >> 2, jl = r & 3;
        const float* wsrc = w_hh + (size_t)(q*HDIM + j0 + jl) * HDIM + ks*32;
#pragma unroll
        for (int i = 0; i < 8; i++)
            wreg[i] = *(const ulonglong2*)(wsrc + i*4);
        const float* wsrc2 = w_ih + (size_t)(q*HDIM + j0 + jl) * FDIM + ks*16;
#pragma unroll
        for (int i = 0; i < 4; i++) {
            ulonglong2 v = *(const ulonglong2*)(wsrc2 + i*4);
            wihreg[2*i]   = v.x;
            wihreg[2*i+1] = v.y;
        }
    }
    if (tid < 32) us[tid] = 1.f;

    const float wuh_l = (tid < 128) ? w_uh[j0 + (tid & 3)] : 0.f;
    const float buh   = b_uh[0];

    float biasr[4];
    if (tid < 128) {
        int jl = tid & 3;
#pragma unroll
        for (int q = 0; q < 4; q++)
            biasr[q] = b_ih[q*HDIM + j0 + jl] + b_hh[q*HDIM + j0 + jl];
    }
    __syncthreads();

    // ---- prologue: xg for t=0 --------------------------------------------
    float xg[4] = {0.f, 0.f, 0.f, 0.f};
    {
        xp_stage(fts, 0, tid);
        __syncthreads();
        xp_dot(fts, part, wihreg, r, ks, b0);
        __syncthreads();
        if (tid < 128) {
            int b = tid >> 2, jl = tid & 3;
#pragma unroll
            for (int q = 0; q < 4; q++) {
                float s = biasr[q];
                const float* pp = part + b*PSTR + q*4 + jl;
#pragma unroll
                for (int k2 = 0; k2 < 16; k2++) s += pp[k2*SKS];
                xg[q] = s;
            }
        }
        __syncthreads();
    }

    float c_reg = 0.f;                   // cell state for (b = tid>>2, jl = tid&3)

    for (int t = 0; t < TPRIME; t++) {
        const int ph = t & 1;

        // ---- load this warp's h slab: h[b][32*warp .. +32], 8 float4/lane ----
        const float4* hsrc = reinterpret_cast<const float4*>(g_h[ph]);
        float4 hv[8];
#pragma unroll
        for (int i = 0; i < 8; i++) {
            int f = i*32 + lane;                 // 0..255
            int b = f >> 3, k4 = f & 7;
            hv[i] = __ldcg(hsrc + b*128 + warp*8 + k4);
        }

        // ---- u update from previous step's partials (tid<128) ----------------
        if (t > 0 && tid < 128) {
            const float4* pp = (const float4*)&g_pu[(t-1)&1][(tid>>2)*NCTA_R + (tid&3)*32];
            float s = 0.f;
#pragma unroll
            for (int i = 0; i < 8; i++) {
                float4 v = __ldcg(pp + i);
                s += v.x + v.y + v.z + v.w;
            }
            s += __shfl_down_sync(0xffffffffu, s, 1);
            s += __shfl_down_sync(0xffffffffu, s, 2);
            if ((tid & 3) == 0) {
                int b = tid >> 2;
                float du = sigf(s + buh);
                float u  = us[b];
                float ub = rintf(u);
                us[b] = ub*du + (1.f-ub)*(u + fminf(du, 1.f-u));
            }
        }

        // ---- stage slab into smem (warp w owns slab w) -----------------------
        {
            float* slab = hs + warp*SLAB;
#pragma unroll
            for (int i = 0; i < 8; i++) {
                int f = i*32 + lane;
                int b = f >> 3, k4 = f & 7;
                *(float4*)&slab[b*HROWS + k4*4] = hv[i];
            }
        }
        __syncthreads();   // all 16 slabs ready (GEMM reads other warps' slabs)

        // ---- GEMM: row r x h[b][ks*32 .. +32], b in [b0, b0+16) --------------
        {
            const float* hbase = hs + ks*SLAB + b0*HROWS;
#pragma unroll
            for (int b4 = 0; b4 < 16; b4 += 4) {
                unsigned long long a0[4], a1[4];
#pragma unroll
                for (int bb = 0; bb < 4; bb++) { a0[bb] = 0ull; a1[bb] = 0ull; }
#pragma unroll
                for (int i = 0; i < 8; i++) {
#pragma unroll
                    for (int bb = 0; bb < 4; bb++) {
                        ulonglong2 hq = *(const ulonglong2*)&hbase[(b4+bb)*HROWS + i*4];
                        ffma2(a0[bb], wreg[i].x, hq.x);
                        ffma2(a1[bb], wreg[i].y, hq.y);
                    }
                }
#pragma unroll
                for (int bb = 0; bb < 4; bb++) {
                    float2 p0 = upk(a0[bb]), p1 = upk(a1[bb]);
                    part[ks*SKS + (b0+b4+bb)*PSTR + r] = (p0.x + p0.y) + (p1.x + p1.y);
                }
            }
        }
        __syncthreads();

        // ---- fused k-reduce + cell update (tid<128: b=tid>>2, jl=tid&3) ------
        if (tid < 128) {
            int b  = tid >> 2;
            int jl = tid & 3;
            float g4[4];
#pragma unroll
            for (int q = 0; q < 4; q++) {
                float s = xg[q];
                const float* pp = part + b*PSTR + q*4 + jl;
#pragma unroll
                for (int k2 = 0; k2 < 16; k2++) s += pp[k2*SKS];
                g4[q] = s;
            }
            float u  = us[b];
            float ub = rintf(u);
            float ct = sigf(g4[1])*c_reg + sigf(g4[0])*tanh_fast(g4[2]);
            float ht = sigf(g4[3])*tanh_fast(ct);
            int hidx = j0 + jl;
            float hprev = hs[(hidx >> 5)*SLAB + b*HROWS + (hidx & 31)];
            float cn = ub*ct + (1.f-ub)*c_reg;
            float hn = ub*ht + (1.f-ub)*hprev;
            c_reg = cn;

            __stcg(&g_h[ph^1][b*HDIM + j0 + jl], hn);
            if (t == TPRIME-1) out[b*HDIM + j0 + jl] = hn;

            float pv = cn * wuh_l;
            pv += __shfl_down_sync(0xffffffffu, pv, 1);
            pv += __shfl_down_sync(0xffffffffu, pv, 2);
            if (jl == 0) __stcg(&g_pu[ph][b*NCTA_R + cta], pv);
        }
        __syncthreads();

        if (t < TPRIME-1) {
            // ---- release flag FIRST ------------------------------------------
            if (tid == 0) {
                asm volatile("st.release.gpu.global.u32 [%0], %1;"
                             :: "l"(&g_flags[cta*32]), "r"((unsigned)(t+1)) : "memory");
            }

            // ---- xp for step t+1 in the barrier's shadow ---------------------
            xp_stage(fts, t+1, tid);
            __syncthreads();
            xp_dot(fts, part, wihreg, r, ks, b0);
            __syncthreads();
            if (tid < 128) {
                int b = tid >> 2, jl = tid & 3;
#pragma unroll
                for (int q = 0; q < 4; q++) {
                    float s = biasr[q];
                    const float* pp = part + b*PSTR + q*4 + jl;
#pragma unroll
                    for (int k2 = 0; k2 < 16; k2++) s += pp[k2*SKS];
                    xg[q] = s;
                }
            }

            // ---- paced poll --------------------------------------------------
            if (tid < NCTA_R) {
                const unsigned tgt = (unsigned)(t+1);
                unsigned v;
                asm volatile("ld.acquire.gpu.global.u32 %0, [%1];"
                             : "=r"(v) : "l"(&g_flags[tid*32]) : "memory");
                while (v < tgt) {
                    __nanosleep(40);
                    asm volatile("ld.acquire.gpu.global.u32 %0, [%1];"
                                 : "=r"(v) : "l"(&g_flags[tid*32]) : "memory");
                }
            }
            __syncthreads();
        }
    }
}

// ---------------- launch -----------------------------------------------------
extern "C" void kernel_launch(void* const* d_in, const int* in_sizes, int n_in,
                              void* d_out, int out_size)
{
    const float* x      = (const float*)d_in[0];
    const float* conv_w = (const float*)d_in[1];
    const float* conv_b = (const float*)d_in[2];
    const float* gam    = (const float*)d_in[3];
    const float* bet    = (const float*)d_in[4];
    const float* mu     = (const float*)d_in[5];
    const float* var    = (const float*)d_in[6];
    const float* w_ih   = (const float*)d_in[7];
    const float* w_hh   = (const float*)d_in[8];
    const float* b_ih   = (const float*)d_in[9];
    const float* b_hh   = (const float*)d_in[10];
    const float* w_uh   = (const float*)d_in[11];
    const float* b_uh   = (const float*)d_in[12];

    const int smem_recur = (16*SLAB + 16*SKS + 16*SKS + 32) * (int)sizeof(float);
    cudaFuncSetAttribute(recur_kernel, cudaFuncAttributeMaxDynamicSharedMemorySize, smem_recur);

    prep_kernel<<<64, 256>>>(conv_w);
    conv_gemm<<<dim3(2, 128), 256>>>(x, conv_b, gam, bet, mu, var);
    recur_kernel<<<NCTA_R, NTH_R, smem_recur>>>(w_hh, w_ih, b_ih, b_hh, w_uh, b_uh,
                                                (float*)d_out);
}

// round 16
// speedup vs baseline: 1.0601x; 1.0564x over previous
#include <cuda_runtime.h>
#include <cstdint>
#include <math.h>

// Problem constants
#define TPRIME 510
#define BATCH  32
#define CIN    128
#define TLEN   1024
#define FDIM   256
#define KCONV  640            // CIN * KW
#define HDIM   512
#define GDIM   2048           // 4*H
#define M_ROWS (TPRIME*BATCH) // 16320
#define NCTA_R 128            // persistent CTAs for recurrence

// recurrence smem layout
// h slice row: 64 floats stored as [0..31][4-float shim][32..63] -> halves at +0 / +36
#define HSW    72             // h slice row stride (floats)
#define HSWARP (32*HSW)       // per-warp slice region
#define PSTR   20             // part: b stride
#define SKS    648            // part: ks stride (32*20 + 8)

// ---------------- packed f32x2 helpers (Blackwell FFMA2 path) ----------------
__device__ __forceinline__ void ffma2(unsigned long long &d,
                                      unsigned long long a,
                                      unsigned long long b) {
    asm("fma.rn.f32x2 %0, %1, %2, %0;" : "+l"(d) : "l"(a), "l"(b));
}
__device__ __forceinline__ unsigned long long pk2(float x) {
    unsigned long long r;
    asm("mov.b64 %0, {%1, %1};" : "=l"(r) : "f"(x));
    return r;
}
__device__ __forceinline__ float2 upk(unsigned long long v) {
    float2 r;
    asm("mov.b64 {%0, %1}, %2;" : "=f"(r.x), "=f"(r.y) : "l"(v));
    return r;
}

// ---------------- scratch -----------------------------------------------------
__device__ float g_Wr[FDIM*KCONV];                    // conv_w transposed [f][k][c]
__device__ float g_feats[(size_t)M_ROWS*FDIM];        // conv output [m][F]
__device__ float g_h[2][BATCH*HDIM];                  // double-buffered hidden state
__device__ float g_pu[2][BATCH*NCTA_R];               // partial u-dot [b][cta]
__device__ unsigned g_flags[NCTA_R*32];               // per-CTA step flags, 128B apart

// ---------------- prep --------------------------------------------------------
__global__ void prep_kernel(const float* __restrict__ conv_w)
{
    int stride = gridDim.x * blockDim.x;
    int i0 = blockIdx.x * blockDim.x + threadIdx.x;
    for (int i = i0; i < FDIM*KCONV; i += stride) {
        int f = i / KCONV;
        int rem = i - f*KCONV;
        int k = rem >> 7;
        int c = rem & 127;
        g_Wr[i] = conv_w[f*KCONV + c*5 + k];
    }
    for (int i = i0; i < BATCH*HDIM; i += stride) g_h[0][i] = 0.f;
    for (int i = i0; i < NCTA_R*32; i += stride) g_flags[i] = 0u;
}

// ---------------- conv as GEMM (double-buffered): [16320x640]*[640x256]^T -----
__global__ __launch_bounds__(256)
void conv_gemm(const float* __restrict__ x,
               const float* __restrict__ cb,
               const float* __restrict__ gam,
               const float* __restrict__ bet,
               const float* __restrict__ mu,
               const float* __restrict__ var)
{
    __shared__ float As[2][16][132];
    __shared__ float Bs[2][16][132];
    const int tid  = threadIdx.x;
    const int mblk = blockIdx.y * 128;
    const int nblk = blockIdx.x * 128;
    const int lrow = tid >> 1;
    const int lk   = (tid & 1) * 8;

    const int m = mblk + lrow;
    const bool mvalid = (m < M_ROWS);
    const float* arow = x;
    if (mvalid) {
        int t = m >> 5, b = m & 31;
        arow = x + (size_t)b * (TLEN*CIN) + (size_t)t * (2*CIN);
    }
    const float* brow = g_Wr + (size_t)(nblk + lrow) * KCONV;

    unsigned long long acc2[8][4];
#pragma unroll
    for (int i = 0; i < 8; i++)
#pragma unroll
        for (int j = 0; j < 4; j++) acc2[i][j] = 0ull;

    const int ty = tid >> 4, tx = tid & 15;

    // prologue: load tile 0 and stage into buffer 0
    float4 a0 = make_float4(0.f,0.f,0.f,0.f), a1 = a0;
    if (mvalid) {
        a0 = *(const float4*)(arow + lk);
        a1 = *(const float4*)(arow + lk + 4);
    }
    float4 b0 = *(const float4*)(brow + lk);
    float4 b1 = *(const float4*)(brow + lk + 4);
    As[0][lk+0][lrow]=a0.x; As[0][lk+1][lrow]=a0.y; As[0][lk+2][lrow]=a0.z; As[0][lk+3][lrow]=a0.w;
    As[0][lk+4][lrow]=a1.x; As[0][lk+5][lrow]=a1.y; As[0][lk+6][lrow]=a1.z; As[0][lk+7][lrow]=a1.w;
    Bs[0][lk+0][lrow]=b0.x; Bs[0][lk+1][lrow]=b0.y; Bs[0][lk+2][lrow]=b0.z; Bs[0][lk+3][lrow]=b0.w;
    Bs[0][lk+4][lrow]=b1.x; Bs[0][lk+5][lrow]=b1.y; Bs[0][lk+6][lrow]=b1.z; Bs[0][lk+7][lrow]=b1.w;
    __syncthreads();

    for (int it = 0; it < KCONV/16; it++) {
        const int cur = it & 1;
        const int nxt = cur ^ 1;
        const bool has_next = (it < KCONV/16 - 1);

        // issue next tile's global loads early (hidden under compute)
        if (has_next) {
            int k0 = (it + 1) * 16;
            a0 = make_float4(0.f,0.f,0.f,0.f); a1 = a0;
            if (mvalid) {
                a0 = *(const float4*)(arow + k0 + lk);
                a1 = *(const float4*)(arow + k0 + lk + 4);
            }
            b0 = *(const float4*)(brow + k0 + lk);
            b1 = *(const float4*)(brow + k0 + lk + 4);
        }

        // compute from buffer cur
#pragma unroll
        for (int k = 0; k < 16; k++) {
            float a[8];
            *(float4*)&a[0] = *(const float4*)&As[cur][k][ty*4];
            *(float4*)&a[4] = *(const float4*)&As[cur][k][ty*4+64];
            ulonglong2 bq0 = *(const ulonglong2*)&Bs[cur][k][tx*4];
            ulonglong2 bq1 = *(const ulonglong2*)&Bs[cur][k][tx*4+64];
#pragma unroll
            for (int i = 0; i < 8; i++) {
                unsigned long long aa = pk2(a[i]);
                ffma2(acc2[i][0], aa, bq0.x);
                ffma2(acc2[i][1], aa, bq0.y);
                ffma2(acc2[i][2], aa, bq1.x);
                ffma2(acc2[i][3], aa, bq1.y);
            }
        }

        // stage next tile into the other buffer; one sync per iteration
        if (has_next) {
            As[nxt][lk+0][lrow]=a0.x; As[nxt][lk+1][lrow]=a0.y; As[nxt][lk+2][lrow]=a0.z; As[nxt][lk+3][lrow]=a0.w;
            As[nxt][lk+4][lrow]=a1.x; As[nxt][lk+5][lrow]=a1.y; As[nxt][lk+6][lrow]=a1.z; As[nxt][lk+7][lrow]=a1.w;
            Bs[nxt][lk+0][lrow]=b0.x; Bs[nxt][lk+1][lrow]=b0.y; Bs[nxt][lk+2][lrow]=b0.z; Bs[nxt][lk+3][lrow]=b0.w;
            Bs[nxt][lk+4][lrow]=b1.x; Bs[nxt][lk+5][lrow]=b1.y; Bs[nxt][lk+6][lrow]=b1.z; Bs[nxt][lk+7][lrow]=b1.w;
            __syncthreads();
        }
    }

    // epilogue: +bias, ReLU, BN affine
#pragma unroll
    for (int j2 = 0; j2 < 4; j2++) {
        int nrel = (j2 < 2) ? (tx*4 + j2*2) : (64 + tx*4 + (j2-2)*2);
#pragma unroll
        for (int h = 0; h < 2; h++) {
            int n = nblk + nrel + h;
            float invv = gam[n] * rsqrtf(var[n] + 1e-5f);
            float addv = bet[n] - mu[n]*invv;
            float cbv  = cb[n];
#pragma unroll
            for (int i = 0; i < 8; i++) {
                int mm = mblk + ((i < 4) ? (ty*4 + i) : (64 + ty*4 + i - 4));
                if (mm < M_ROWS) {
                    float2 p = upk(acc2[i][j2]);
                    float v = ((h == 0) ? p.x : p.y) + cbv;
                    v = fmaxf(v, 0.f);
                    g_feats[(size_t)mm*FDIM + n] = v*invv + addv;
                }
            }
        }
    }
}

// ---------------- persistent skip-LSTM recurrence (xproj fused in) ------------
__device__ __forceinline__ float sigf(float v) {
    return __fdividef(1.f, 1.f + __expf(-v));
}
__device__ __forceinline__ float tanh_fast(float v) {
    float x = fminf(fmaxf(v, -15.f), 15.f);
    float e = __expf(2.f * x);
    return __fdividef(e - 1.f, e + 1.f);
}

// xp tail: stage feats[tt] -> fts, dot with register-resident w_ih slices.
__device__ __forceinline__ void xp_stage(float* fts, int tt, int tid)
{
    const float4* fsrc = reinterpret_cast<const float4*>(g_feats) + (size_t)tt * 2048;
#pragma unroll
    for (int i = 0; i < 8; i++) {
        int f = i*256 + tid;                 // float4 index: b = f>>6, k4 = f&63
        float4 v = __ldcg(fsrc + f);
        int b = f >> 6, k4 = f & 63;
        *(float4*)&fts[(size_t)(k4 >> 2)*SKS + b*PSTR + (k4 & 3)*4] = v;
    }
}

__device__ __forceinline__ void xp_dot(const float* fts, float* part,
                                       const unsigned long long* wihreg,
                                       int r, int ks)
{
    const float* fb = fts + ks*SKS;
#pragma unroll 4
    for (int b = 0; b < 32; b++) {
        const float* fp = fb + b*PSTR;
        ulonglong2 f0 = *(const ulonglong2*)(fp);
        ulonglong2 f1 = *(const ulonglong2*)(fp + 4);
        ulonglong2 f2 = *(const ulonglong2*)(fp + 8);
        ulonglong2 f3 = *(const ulonglong2*)(fp + 12);
        unsigned long long a = 0ull;
        ffma2(a, wihreg[0], f0.x); ffma2(a, wihreg[1], f0.y);
        ffma2(a, wihreg[2], f1.x); ffma2(a, wihreg[3], f1.y);
        ffma2(a, wihreg[4], f2.x); ffma2(a, wihreg[5], f2.y);
        ffma2(a, wihreg[6], f3.x); ffma2(a, wihreg[7], f3.y);
        float2 p = upk(a);
        part[ks*SKS + b*PSTR + r] = p.x + p.y;
    }
}

__global__ __launch_bounds__(256)
void recur_kernel(const float* __restrict__ w_hh,
                  const float* __restrict__ w_ih,
                  const float* __restrict__ b_ih,
                  const float* __restrict__ b_hh,
                  const float* __restrict__ w_uh,
                  const float* __restrict__ b_uh,
                  float* __restrict__ out)
{
    extern __shared__ float sm[];
    float* hs   = sm;                    // [8 warps][32 b][HSW]   h slices (shimmed)
    float* part = hs + 8*HSWARP;         // [16 ks][32 b][PSTR]
    float* fts  = part + 16*SKS;         // [16 ks][32 b][PSTR]    feats tile
    float* us   = fts + 16*SKS;          // [32] u state

    const int tid  = threadIdx.x;
    const int warp = tid >> 5;
    const int lane = tid & 31;
    const int cta  = blockIdx.x;
    const int j0   = cta * 4;

    const int r  = tid & 15;             // row 0..15 (q = r>>2, jl = r&3)
    const int ks = tid >> 4;             // k-slice 0..15

    ulonglong2 wreg[8];
    unsigned long long wihreg[8];
    {
        int q = r >> 2, jl = r & 3;
        const float* wsrc = w_hh + (size_t)(q*HDIM + j0 + jl) * HDIM + ks*32;
#pragma unroll
        for (int i = 0; i < 8; i++)
            wreg[i] = *(const ulonglong2*)(wsrc + i*4);
        const float* wsrc2 = w_ih + (size_t)(q*HDIM + j0 + jl) * FDIM + ks*16;
#pragma unroll
        for (int i = 0; i < 4; i++) {
            ulonglong2 v = *(const ulonglong2*)(wsrc2 + i*4);
            wihreg[2*i]   = v.x;
            wihreg[2*i+1] = v.y;
        }
    }
    if (tid < 32) us[tid] = 1.f;

    const float wuh_l = (tid < 128) ? w_uh[j0 + (tid & 3)] : 0.f;
    const float buh   = b_uh[0];

    float biasr[4];
    if (tid < 128) {
        int jl = tid & 3;
#pragma unroll
        for (int q = 0; q < 4; q++)
            biasr[q] = b_ih[q*HDIM + j0 + jl] + b_hh[q*HDIM + j0 + jl];
    }
    __syncthreads();

    // ---- prologue: xg for t=0 --------------------------------------------
    float xg[4] = {0.f, 0.f, 0.f, 0.f};
    {
        xp_stage(fts, 0, tid);
        __syncthreads();
        xp_dot(fts, part, wihreg, r, ks);
        __syncthreads();
        if (tid < 128) {
            int b = tid >> 2, jl = tid & 3;
#pragma unroll
            for (int q = 0; q < 4; q++) {
                float s = biasr[q];
                const float* pp = part + b*PSTR + q*4 + jl;
#pragma unroll
                for (int k2 = 0; k2 < 16; k2++) s += pp[k2*SKS];
                xg[q] = s;
            }
        }
        __syncthreads();
    }

    float c_reg = 0.f;
    float* hswp = hs + warp*HSWARP;

    for (int t = 0; t < TPRIME; t++) {
        const int ph = t & 1;

        const float4* hsrc = reinterpret_cast<const float4*>(g_h[ph]);
        float4 hv[16];
#pragma unroll
        for (int i = 0; i < 16; i++) {
            int f = i*32 + lane;
            int b = f >> 4, k4 = f & 15;
            hv[i] = __ldcg(hsrc + b*128 + warp*16 + k4);
        }

        if (t > 0 && tid < 128) {
            const float4* pp = (const float4*)&g_pu[(t-1)&1][(tid>>2)*NCTA_R + (tid&3)*32];
            float s = 0.f;
#pragma unroll
            for (int i = 0; i < 8; i++) {
                float4 v = __ldcg(pp + i);
                s += v.x + v.y + v.z + v.w;
            }
            s += __shfl_down_sync(0xffffffffu, s, 1);
            s += __shfl_down_sync(0xffffffffu, s, 2);
            if ((tid & 3) == 0) {
                int b = tid >> 2;
                float du = sigf(s + buh);
                float u  = us[b];
                float ub = rintf(u);
                us[b] = ub*du + (1.f-ub)*(u + fminf(du, 1.f-u));
            }
        }

#pragma unroll
        for (int i = 0; i < 16; i++) {
            int f = i*32 + lane;
            int b = f >> 4, k4 = f & 15;
            int off = k4*4 + ((k4 >> 3) << 2);
            *(float4*)&hswp[b*HSW + off] = hv[i];
        }
        __syncwarp();

        const float* hbase = hswp + (ks & 1)*36;
#pragma unroll 4
        for (int b4 = 0; b4 < 32; b4 += 4) {
            unsigned long long a0[4], a1[4];
#pragma unroll
            for (int bb = 0; bb < 4; bb++) { a0[bb] = 0ull; a1[bb] = 0ull; }
#pragma unroll
            for (int i = 0; i < 8; i++) {
#pragma unroll
                for (int bb = 0; bb < 4; bb++) {
                    ulonglong2 hq = *(const ulonglong2*)&hbase[(b4+bb)*HSW + i*4];
                    ffma2(a0[bb], wreg[i].x, hq.x);
                    ffma2(a1[bb], wreg[i].y, hq.y);
                }
            }
#pragma unroll
            for (int bb = 0; bb < 4; bb++) {
                float2 p0 = upk(a0[bb]), p1 = upk(a1[bb]);
                part[ks*SKS + (b4+bb)*PSTR + r] = (p0.x + p0.y) + (p1.x + p1.y);
            }
        }
        __syncthreads();

        if (tid < 128) {
            int b  = tid >> 2;
            int jl = tid & 3;
            float g4[4];
#pragma unroll
            for (int q = 0; q < 4; q++) {
                float s = xg[q];
                const float* pp = part + b*PSTR + q*4 + jl;
#pragma unroll
                for (int k2 = 0; k2 < 16; k2++) s += pp[k2*SKS];
                g4[q] = s;
            }
            float u  = us[b];
            float ub = rintf(u);
            float ct = sigf(g4[1])*c_reg + sigf(g4[0])*tanh_fast(g4[2]);
            float ht = sigf(g4[3])*tanh_fast(ct);
            int hidx = j0 + jl;
            int hw = hidx >> 6;
            int ho = hidx & 63;
            int hoff = ho + ((ho >> 5) << 2);
            float hprev = hs[hw*HSWARP + b*HSW + hoff];
            float cn = ub*ct + (1.f-ub)*c_reg;
            float hn = ub*ht + (1.f-ub)*hprev;
            c_reg = cn;

            __stcg(&g_h[ph^1][b*HDIM + j0 + jl], hn);
            if (t == TPRIME-1) out[b*HDIM + j0 + jl] = hn;

            float pv = cn * wuh_l;
            pv += __shfl_down_sync(0xffffffffu, pv, 1);
            pv += __shfl_down_sync(0xffffffffu, pv, 2);
            if (jl == 0) __stcg(&g_pu[ph][b*NCTA_R + cta], pv);
        }
        __syncthreads();

        if (t < TPRIME-1) {
            if (tid == 0) {
                asm volatile("st.release.gpu.global.u32 [%0], %1;"
                             :: "l"(&g_flags[cta*32]), "r"((unsigned)(t+1)) : "memory");
            }

            xp_stage(fts, t+1, tid);
            __syncthreads();
            xp_dot(fts, part, wihreg, r, ks);
            __syncthreads();
            if (tid < 128) {
                int b = tid >> 2, jl = tid & 3;
#pragma unroll
                for (int q = 0; q < 4; q++) {
                    float s = biasr[q];
                    const float* pp = part + b*PSTR + q*4 + jl;
#pragma unroll
                    for (int k2 = 0; k2 < 16; k2++) s += pp[k2*SKS];
                    xg[q] = s;
                }
            }

            if (tid < NCTA_R) {
                const unsigned tgt = (unsigned)(t+1);
                unsigned v;
                asm volatile("ld.acquire.gpu.global.u32 %0, [%1];"
                             : "=r"(v) : "l"(&g_flags[tid*32]) : "memory");
                while (v < tgt) {
                    __nanosleep(40);
                    asm volatile("ld.acquire.gpu.global.u32 %0, [%1];"
                                 : "=r"(v) : "l"(&g_flags[tid*32]) : "memory");
                }
            }
            __syncthreads();
        }
    }
}

// ---------------- launch -----------------------------------------------------
extern "C" void kernel_launch(void* const* d_in, const int* in_sizes, int n_in,
                              void* d_out, int out_size)
{
    const float* x      = (const float*)d_in[0];
    const float* conv_w = (const float*)d_in[1];
    const float* conv_b = (const float*)d_in[2];
    const float* gam    = (const float*)d_in[3];
    const float* bet    = (const float*)d_in[4];
    const float* mu     = (const float*)d_in[5];
    const float* var    = (const float*)d_in[6];
    const float* w_ih   = (const float*)d_in[7];
    const float* w_hh   = (const float*)d_in[8];
    const float* b_ih   = (const float*)d_in[9];
    const float* b_hh   = (const float*)d_in[10];
    const float* w_uh   = (const float*)d_in[11];
    const float* b_uh   = (const float*)d_in[12];

    const int smem_recur = (8*HSWARP + 16*SKS + 16*SKS + 32) * (int)sizeof(float);
    cudaFuncSetAttribute(recur_kernel, cudaFuncAttributeMaxDynamicSharedMemorySize, smem_recur);

    prep_kernel<<<64, 256>>>(conv_w);
    conv_gemm<<<dim3(2, 128), 256>>>(x, conv_b, gam, bet, mu, var);
    recur_kernel<<<NCTA_R, 256, smem_recur>>>(w_hh, w_ih, b_ih, b_hh, w_uh, b_uh,
                                              (float*)d_out);
}